// round 1
// baseline (speedup 1.0000x reference)
#include <cuda_runtime.h>
#include <cuda_bf16.h>
#include <math.h>

// Problem constants (fixed shapes from reference)
#define B_   64
#define M_   80
#define TOUT 2000
#define TIN  400

#define N_MEL   (B_ * M_ * TOUT)          // 10,240,000
#define N_MEL4  (N_MEL / 4)               // 2,560,000
#define N_GATE  (B_ * TOUT)               // 128,000
#define N_GATE4 (N_GATE / 4)              // 32,000
#define N_AL    (B_ * TOUT * TIN)         // 51,200,000
#define N_AL4   (N_AL / 4)                // 12,800,000
#define TIN4    (TIN / 4)                 // 100

#define INV2SIG2 3.125f                   // 1/(2*0.4^2)

// Accumulators: 0=mel1, 1=mel2, 2=gate, 3=att, 4=ga
__device__ double g_acc[5];

__global__ void init_kernel() {
    if (threadIdx.x < 5) g_acc[threadIdx.x] = 0.0;
}

__device__ __forceinline__ float warp_sum(float v) {
    #pragma unroll
    for (int o = 16; o > 0; o >>= 1)
        v += __shfl_xor_sync(0xFFFFFFFFu, v, o);
    return v;
}

// block reduce 2 values -> one atomicAdd(double) each by thread 0
__device__ __forceinline__ void block_reduce2_atomic(float a, float b, int idx_a, int idx_b) {
    __shared__ float sa[32], sb[32];
    int lane = threadIdx.x & 31;
    int wid  = threadIdx.x >> 5;
    a = warp_sum(a);
    b = warp_sum(b);
    if (lane == 0) { sa[wid] = a; sb[wid] = b; }
    __syncthreads();
    int nw = blockDim.x >> 5;
    if (wid == 0) {
        a = (lane < nw) ? sa[lane] : 0.0f;
        b = (lane < nw) ? sb[lane] : 0.0f;
        a = warp_sum(a);
        b = warp_sum(b);
        if (lane == 0) {
            atomicAdd(&g_acc[idx_a], (double)a);
            atomicAdd(&g_acc[idx_b], (double)b);
        }
    }
}

// ---------------- Mel L1 (decoder + postnet), fused single pass ----------------
__global__ void mel_kernel(const float4* __restrict__ mo,
                           const float4* __restrict__ mp,
                           const float4* __restrict__ mt) {
    float s1 = 0.0f, s2 = 0.0f;
    int stride = gridDim.x * blockDim.x;
    for (int i = blockIdx.x * blockDim.x + threadIdx.x; i < N_MEL4; i += stride) {
        float4 a = mo[i];
        float4 p = mp[i];
        float4 t = mt[i];
        s1 += fabsf(a.x - t.x) + fabsf(a.y - t.y) + fabsf(a.z - t.z) + fabsf(a.w - t.w);
        s2 += fabsf(p.x - t.x) + fabsf(p.y - t.y) + fabsf(p.z - t.z) + fabsf(p.w - t.w);
    }
    block_reduce2_atomic(s1, s2, 0, 1);
}

// ---------------- Gate BCE-with-logits ----------------
__device__ __forceinline__ float bce1(float x, float z) {
    return fmaxf(x, 0.0f) - x * z + log1pf(expf(-fabsf(x)));
}

__global__ void gate_kernel(const float4* __restrict__ go,
                            const float4* __restrict__ gt) {
    float s = 0.0f;
    int stride = gridDim.x * blockDim.x;
    for (int i = blockIdx.x * blockDim.x + threadIdx.x; i < N_GATE4; i += stride) {
        float4 x = go[i];
        float4 z = gt[i];
        s += bce1(x.x, z.x) + bce1(x.y, z.y) + bce1(x.z, z.z) + bce1(x.w, z.w);
    }
    // reduce single value (reuse helper with a dummy zero into same slot is wasteful;
    // do a dedicated path)
    __shared__ float sh[32];
    int lane = threadIdx.x & 31, wid = threadIdx.x >> 5;
    s = warp_sum(s);
    if (lane == 0) sh[wid] = s;
    __syncthreads();
    if (wid == 0) {
        int nw = blockDim.x >> 5;
        s = (lane < nw) ? sh[lane] : 0.0f;
        s = warp_sum(s);
        if (lane == 0) atomicAdd(&g_acc[2], (double)s);
    }
}

// ---------------- Alignments: backward-mask sum + guided-attention sum ----------------
__global__ void align_kernel(const float4* __restrict__ al,
                             const int*    __restrict__ in_len,
                             const int*    __restrict__ out_len) {
    float s_att = 0.0f, s_ga = 0.0f;
    int stride = gridDim.x * blockDim.x;
    for (int idx = blockIdx.x * blockDim.x + threadIdx.x; idx < N_AL4; idx += stride) {
        int j4  = idx % TIN4;               // 0..99
        int row = idx / TIN4;               // b*TOUT + i
        int i   = row % TOUT;
        int b   = row / TOUT;

        float4 a = al[idx];
        int j0 = j4 * 4;

        // attention (strictly below diagonal): j < i
        // j0..j0+3 vs i
        if (j0 + 3 < i) {
            s_att += a.x + a.y + a.z + a.w;
        } else {
            if (j0 + 0 < i) s_att += a.x;
            if (j0 + 1 < i) s_att += a.y;
            if (j0 + 2 < i) s_att += a.z;
            if (j0 + 3 < i) s_att += a.w;
        }

        // guided attention
        int li = in_len[b];
        int lo = out_len[b];
        if (i < lo) {
            float scale = (float)lo / (float)li;
            float fi = (float)i;
            #pragma unroll
            for (int k = 0; k < 4; k++) {
                int j = j0 + k;
                if (j < li) {
                    float d = fi - (float)j * scale;
                    float w = 1.0f - __expf(-d * d * INV2SIG2);
                    float av = (k == 0) ? a.x : (k == 1) ? a.y : (k == 2) ? a.z : a.w;
                    s_ga += av * w;
                }
            }
        }
    }
    block_reduce2_atomic(s_att, s_ga, 3, 4);
}

// ---------------- Finalize ----------------
__global__ void finalize_kernel(float* __restrict__ out) {
    if (threadIdx.x == 0 && blockIdx.x == 0) {
        double mel  = (g_acc[0] + g_acc[1]) / (double)N_MEL;
        double gate = g_acc[2] / (double)N_GATE;
        double att  = g_acc[3] / (double)B_;
        double ga   = g_acc[4] / (double)B_;
        double total = mel + gate + 0.1 * att + 0.1 * ga;
        out[0] = (float)total;
        out[1] = (float)mel;
        out[2] = (float)gate;
        out[3] = (float)att;
        out[4] = (float)ga;
    }
}

extern "C" void kernel_launch(void* const* d_in, const int* in_sizes, int n_in,
                              void* d_out, int out_size) {
    const float* mel_out         = (const float*)d_in[0];
    const float* mel_out_postnet = (const float*)d_in[1];
    const float* gate_out        = (const float*)d_in[2];
    const float* alignments      = (const float*)d_in[3];
    const float* mel_target      = (const float*)d_in[4];
    const float* gate_target     = (const float*)d_in[5];
    const int*   input_lengths   = (const int*)d_in[6];
    const int*   output_lengths  = (const int*)d_in[7];
    float* out = (float*)d_out;

    init_kernel<<<1, 32>>>();

    mel_kernel<<<4096, 256>>>((const float4*)mel_out,
                              (const float4*)mel_out_postnet,
                              (const float4*)mel_target);

    gate_kernel<<<125, 256>>>((const float4*)gate_out,
                              (const float4*)gate_target);

    align_kernel<<<8192, 256>>>((const float4*)alignments,
                                input_lengths, output_lengths);

    finalize_kernel<<<1, 32>>>(out);
}